// round 3
// baseline (speedup 1.0000x reference)
#include <cuda_runtime.h>
#include <cuda_bf16.h>
#include <cstring>

#define N_NODES 5000
#define N_EDGES 30000
#define HID     64      // hidden
#define ED      16      // edge dim
#define H2      4096    // hidden^2
#define NCOLS   262144  // 4096*64 columns of M

// ---------------- static device scratch (no allocs allowed) ----------------
// IMPORTANT: every __device__ global gets a full-size HOST shadow symbol.
// Total static memory must stay well under 2 GB or the host link fails
// (GOTPCREL relocation overflow). We therefore process nodes in passes of
// PASS_NODES through one reusable M scratch buffer.
#define PASS_NODES 1024
#define N_PASSES   ((N_NODES + PASS_NODES - 1) / PASS_NODES)   // 5
__device__ __align__(16) float g_M[(size_t)PASS_NODES * NCOLS];   // 1.07 GB
__device__ __align__(16) float g_hid[(size_t)N_EDGES * H2];       // 491.5 MB

__device__ int g_cnt[N_NODES];
__device__ int g_off[N_NODES + 1];
__device__ int g_cur[N_NODES];
__device__ int g_perm[N_EDGES];

__device__ __forceinline__ void ffma2(unsigned long long& d,
                                      unsigned long long a,
                                      unsigned long long b) {
    // packed f32x2 FMA: d.lo = a.lo*b.lo + d.lo ; d.hi = a.hi*b.hi + d.hi
    asm volatile("fma.rn.f32x2 %0, %1, %2, %0;" : "+l"(d) : "l"(a), "l"(b));
}

// ---------------- CSR build (group edges by src node) ----------------
__global__ void k_zero_cnt() {
    int i = blockIdx.x * blockDim.x + threadIdx.x;
    if (i < N_NODES) g_cnt[i] = 0;
}

__global__ void k_hist(const int* __restrict__ ei) {
    int e = blockIdx.x * blockDim.x + threadIdx.x;
    if (e < N_EDGES) atomicAdd(&g_cnt[ei[e]], 1);   // ei[0..E) = src
}

__global__ void k_scan() {
    __shared__ int ts[1024];
    int t = threadIdx.x;
    int c[5];
    int base = t * 5;
    int s = 0;
#pragma unroll
    for (int u = 0; u < 5; u++) {
        int id = base + u;
        c[u] = (id < N_NODES) ? g_cnt[id] : 0;
        s += c[u];
    }
    ts[t] = s;
    __syncthreads();
    for (int ofs = 1; ofs < 1024; ofs <<= 1) {
        int v = (t >= ofs) ? ts[t - ofs] : 0;
        __syncthreads();
        ts[t] += v;
        __syncthreads();
    }
    int ex = ts[t] - s;   // exclusive prefix
#pragma unroll
    for (int u = 0; u < 5; u++) {
        int id = base + u;
        if (id < N_NODES) { g_off[id] = ex; g_cur[id] = ex; }
        ex += c[u];
    }
    if (t == 0) g_off[N_NODES] = N_EDGES;
}

__global__ void k_scatter(const int* __restrict__ ei) {
    int e = blockIdx.x * blockDim.x + threadIdx.x;
    if (e < N_EDGES) {
        int pos = atomicAdd(&g_cur[ei[e]], 1);
        g_perm[pos] = e;
    }
}

// ---------------- hid = relu(edge_attr @ W1 + b1) ----------------
#define HID_EB 8
__global__ void k_hid(const float* __restrict__ ea,
                      const float* __restrict__ W1,
                      const float* __restrict__ b1) {
    __shared__ float eaS[HID_EB][ED];
    int e0 = blockIdx.x * HID_EB;
    int tid = threadIdx.x;
    if (tid < HID_EB * ED) {
        int e = tid / ED, t = tid % ED;
        eaS[e][t] = ea[(size_t)(e0 + e) * ED + t];
    }
    __syncthreads();
    for (int k = tid; k < H2; k += 256) {
        float acc[HID_EB];
        float bv = b1[k];
#pragma unroll
        for (int e = 0; e < HID_EB; e++) acc[e] = bv;
#pragma unroll
        for (int t = 0; t < ED; t++) {
            float w = W1[t * H2 + k];
#pragma unroll
            for (int e = 0; e < HID_EB; e++) acc[e] = fmaf(eaS[e][t], w, acc[e]);
        }
#pragma unroll
        for (int e = 0; e < HID_EB; e++)
            g_hid[(size_t)(e0 + e) * H2 + k] = fmaxf(acc[e], 0.0f);
    }
}

// ---------------- GEMM1: M[n, c] = sum_j h[n,j] * W2.flat[c*64 + j] ----------------
// Tile 64 nodes x 256 cols, K = 64. fp32 exact via packed fma.rn.f32x2.
// A in smem as node-pairs (8B), B in smem duplicated (b,b) (8B).
#define G1_TN 64
#define G1_TC 256
#define A_PITCH 33    // ull pairs per j row (32 pairs + 1 pad)
#define B_PITCH 257   // ull entries per j row (256 + 1 pad)
#define G1_SMEM ((64 * A_PITCH + 64 * B_PITCH) * 8)   // 148,480 B

__global__ void __launch_bounds__(256, 1) k_gemm1(const float* __restrict__ h,
                                                  const float* __restrict__ W2,
                                                  int n_base) {
    extern __shared__ unsigned long long sm[];
    unsigned long long* As2 = sm;                  // [64][A_PITCH]
    unsigned long long* Bsd = sm + 64 * A_PITCH;   // [64][B_PITCH]

    int tid = threadIdx.x;
    int tx = tid & 31;           // col lane
    int ty = tid >> 5;           // node group (8 nodes each)
    int n0 = n_base + blockIdx.y * G1_TN;
    size_t c0 = (size_t)blockIdx.x * G1_TC;

    // fill A (transposed, packed by node-pairs)
    float* As2f = (float*)As2;
    for (int idx = tid; idx < G1_TN * 64; idx += 256) {
        int n = idx >> 6, j = idx & 63;
        float v = (n0 + n < N_NODES) ? h[(size_t)(n0 + n) * 64 + j] : 0.0f;
        As2f[(j * A_PITCH + (n >> 1)) * 2 + (n & 1)] = v;
    }
    // fill B (transposed, duplicated)
    float2* Bsdf = (float2*)Bsd;
    for (int idx = tid; idx < G1_TC * 64; idx += 256) {
        int c = idx >> 6, j = idx & 63;
        float v = W2[(c0 + c) * 64 + j];
        Bsdf[j * B_PITCH + c] = make_float2(v, v);
    }
    __syncthreads();

    unsigned long long acc[4][8];
#pragma unroll
    for (int p = 0; p < 4; p++)
#pragma unroll
        for (int k = 0; k < 8; k++) acc[p][k] = 0ull;

    for (int j = 0; j < 64; j++) {
        unsigned long long a[4], b[8];
#pragma unroll
        for (int p = 0; p < 4; p++) a[p] = As2[j * A_PITCH + ty * 4 + p];
#pragma unroll
        for (int k = 0; k < 8; k++) b[k] = Bsd[j * B_PITCH + tx + 32 * k];
#pragma unroll
        for (int p = 0; p < 4; p++)
#pragma unroll
            for (int k = 0; k < 8; k++) ffma2(acc[p][k], a[p], b[k]);
    }

#pragma unroll
    for (int p = 0; p < 4; p++) {
        int ne = n0 + ty * 8 + 2 * p;      // even node of the pair
        if (ne >= N_NODES) continue;
        float* r0 = g_M + (size_t)(ne - n_base) * NCOLS + c0 + tx;
        float* r1 = (ne + 1 < N_NODES)
                        ? (g_M + (size_t)(ne + 1 - n_base) * NCOLS + c0 + tx)
                        : nullptr;
#pragma unroll
        for (int k = 0; k < 8; k++) {
            float2 v;
            memcpy(&v, &acc[p][k], 8);
            r0[32 * k] = v.x;
            if (r1) r1[32 * k] = v.y;
        }
    }
}

// ---------------- Stage 2: per-node, m[e,i] = sum_k hid[e,k]*M[n,k*64+i] + cb[i] ----------------
// 256 threads = 8 edge slots x 32 lanes (each lane owns i pair {2*il, 2*il+1}).
// Up to 3 register accumulators per thread -> 24 edges per M pass.
__global__ void __launch_bounds__(256) k_stage2(const float* __restrict__ h,
                                                const float* __restrict__ b2,
                                                float* __restrict__ out,
                                                int n_base) {
    __shared__ __align__(16) float Ms[128 * 64];     // 32 KB M chunk [k][i]
    __shared__ __align__(16) float hidS[24 * 128];   // 12 KB hid chunk [slot][k]
    __shared__ float hS[64];
    __shared__ float cb[64];
    __shared__ int eS[24];

    int n = n_base + blockIdx.x;
    if (n >= N_NODES) return;
    int start = g_off[n], end = g_off[n + 1];
    if (start == end) return;

    int tid = threadIdx.x;
    int s = tid >> 5;
    int il = tid & 31;
    int i2 = il * 2;

    if (tid < 64) hS[tid] = h[(size_t)n * 64 + tid];
    __syncthreads();
    if (s == 0) {
        float c0 = 0.f, c1 = 0.f;
#pragma unroll 8
        for (int j = 0; j < 64; j++) {
            float hv = hS[j];
            c0 = fmaf(b2[i2 * 64 + j], hv, c0);
            c1 = fmaf(b2[(i2 + 1) * 64 + j], hv, c1);
        }
        cb[i2] = c0; cb[i2 + 1] = c1;
    }

    const float* Mrow = g_M + (size_t)(n - n_base) * NCOLS;

    for (int base = start; base < end; base += 24) {
        int cnt = min(24, end - base);
        __syncthreads();
        if (tid < cnt) eS[tid] = g_perm[base + tid];
        __syncthreads();

        float2 a0 = make_float2(cb[i2], cb[i2 + 1]);
        float2 a1 = a0, a2 = a0;
        bool v0 = (s < cnt), v1 = (s + 8 < cnt), v2 = (s + 16 < cnt);

        for (int kc = 0; kc < 32; kc++) {
            __syncthreads();
            // load M chunk (contiguous 8192 floats)
            const float4* msrc = (const float4*)(Mrow + (size_t)kc * 8192);
            for (int u = tid; u < 2048; u += 256) ((float4*)Ms)[u] = msrc[u];
            // load hid chunk for active edges
            for (int u = tid; u < cnt * 32; u += 256) {
                int v = u >> 5, q = u & 31;
                const float4* hsrc =
                    (const float4*)(g_hid + (size_t)eS[v] * H2 + kc * 128);
                ((float4*)(hidS + v * 128))[q] = hsrc[q];
            }
            __syncthreads();
            if (v0) {
#pragma unroll 4
                for (int k = 0; k < 128; k++) {
                    float2 mm = *(const float2*)&Ms[k * 64 + i2];
                    float h0 = hidS[s * 128 + k];
                    a0.x = fmaf(h0, mm.x, a0.x);
                    a0.y = fmaf(h0, mm.y, a0.y);
                    if (v1) {
                        float h1 = hidS[(s + 8) * 128 + k];
                        a1.x = fmaf(h1, mm.x, a1.x);
                        a1.y = fmaf(h1, mm.y, a1.y);
                    }
                    if (v2) {
                        float h2v = hidS[(s + 16) * 128 + k];
                        a2.x = fmaf(h2v, mm.x, a2.x);
                        a2.y = fmaf(h2v, mm.y, a2.y);
                    }
                }
            }
        }
        if (v0) *(float2*)&out[(size_t)eS[s] * 64 + i2] = a0;
        if (v1) *(float2*)&out[(size_t)eS[s + 8] * 64 + i2] = a1;
        if (v2) *(float2*)&out[(size_t)eS[s + 16] * 64 + i2] = a2;
    }
}

// ---------------- dst passthrough (second tuple element, as float) ----------------
__global__ void k_dst(const int* __restrict__ ei, float* __restrict__ out) {
    int e = blockIdx.x * blockDim.x + threadIdx.x;
    if (e < N_EDGES) out[(size_t)N_EDGES * 64 + e] = (float)ei[N_EDGES + e];
}

// ---------------- launch ----------------
extern "C" void kernel_launch(void* const* d_in, const int* in_sizes, int n_in,
                              void* d_out, int out_size) {
    const float* h  = (const float*)d_in[0];
    const int*   ei = (const int*)d_in[1];
    const float* ea = (const float*)d_in[2];
    const float* W1 = (const float*)d_in[3];
    const float* b1 = (const float*)d_in[4];
    const float* W2 = (const float*)d_in[5];
    const float* b2 = (const float*)d_in[6];
    float* out = (float*)d_out;

    // CSR by src
    k_zero_cnt<<<(N_NODES + 255) / 256, 256>>>();
    k_hist<<<(N_EDGES + 255) / 256, 256>>>(ei);
    k_scan<<<1, 1024>>>();
    k_scatter<<<(N_EDGES + 255) / 256, 256>>>(ei);

    // hid
    k_hid<<<N_EDGES / HID_EB, 256>>>(ea, W1, b1);

    // GEMM1 needs >48KB dynamic smem
    cudaFuncSetAttribute(k_gemm1, cudaFuncAttributeMaxDynamicSharedMemorySize,
                         G1_SMEM);

    // node passes through the reusable M scratch
    for (int p = 0; p < N_PASSES; p++) {
        int n_base = p * PASS_NODES;
        dim3 g1(NCOLS / G1_TC, PASS_NODES / G1_TN);
        k_gemm1<<<g1, 256, G1_SMEM>>>(h, W2, n_base);
        k_stage2<<<PASS_NODES, 256>>>(h, b2, out, n_base);
    }

    if (out_size > N_EDGES * 64)
        k_dst<<<(N_EDGES + 255) / 256, 256>>>(ei, out);
}

// round 4
// speedup vs baseline: 1.2521x; 1.2521x over previous
#include <cuda_runtime.h>
#include <cuda_bf16.h>
#include <cstring>
#include <cstdint>

#define N_NODES 5000
#define N_EDGES 30000
#define HID     64      // hidden
#define ED      16      // edge dim
#define H2      4096    // hidden^2
#define NCOLS   262144  // 4096*64 columns of M

// ---------------- static device scratch (no allocs allowed) ----------------
// Host shadow symbols exist for every __device__ global: keep total < ~1.6 GB
// or the host link fails (GOTPCREL overflow). Nodes processed in passes of
// PASS_NODES through one reusable M buffer.
#define PASS_NODES 1024
#define N_PASSES   ((N_NODES + PASS_NODES - 1) / PASS_NODES)   // 5
__device__ __align__(16) float g_M[(size_t)PASS_NODES * NCOLS];   // 1.07 GB
__device__ __align__(16) float g_hid[(size_t)N_EDGES * H2];       // 491.5 MB

__device__ int g_cnt[N_NODES];
__device__ int g_off[N_NODES + 1];
__device__ int g_cur[N_NODES];
__device__ int g_perm[N_EDGES];

// ---------------- tf32 helpers ----------------
__device__ __forceinline__ uint32_t tf32_rna(float x) {
    uint32_t u;
    asm("cvt.rna.tf32.f32 %0, %1;" : "=r"(u) : "f"(x));
    return u;
}

__device__ __forceinline__ void mma_tf32(float* c,
                                         uint32_t a0, uint32_t a1,
                                         uint32_t a2, uint32_t a3,
                                         uint32_t b0, uint32_t b1) {
    asm volatile(
        "mma.sync.aligned.m16n8k8.row.col.f32.tf32.tf32.f32 "
        "{%0,%1,%2,%3},{%4,%5,%6,%7},{%8,%9},{%0,%1,%2,%3};"
        : "+f"(c[0]), "+f"(c[1]), "+f"(c[2]), "+f"(c[3])
        : "r"(a0), "r"(a1), "r"(a2), "r"(a3), "r"(b0), "r"(b1));
}

// ---------------- CSR build (group edges by src node) ----------------
__global__ void k_zero_cnt() {
    int i = blockIdx.x * blockDim.x + threadIdx.x;
    if (i < N_NODES) g_cnt[i] = 0;
}

__global__ void k_hist(const int* __restrict__ ei) {
    int e = blockIdx.x * blockDim.x + threadIdx.x;
    if (e < N_EDGES) atomicAdd(&g_cnt[ei[e]], 1);   // ei[0..E) = src
}

__global__ void k_scan() {
    __shared__ int ts[1024];
    int t = threadIdx.x;
    int c[5];
    int base = t * 5;
    int s = 0;
#pragma unroll
    for (int u = 0; u < 5; u++) {
        int id = base + u;
        c[u] = (id < N_NODES) ? g_cnt[id] : 0;
        s += c[u];
    }
    ts[t] = s;
    __syncthreads();
    for (int ofs = 1; ofs < 1024; ofs <<= 1) {
        int v = (t >= ofs) ? ts[t - ofs] : 0;
        __syncthreads();
        ts[t] += v;
        __syncthreads();
    }
    int ex = ts[t] - s;
#pragma unroll
    for (int u = 0; u < 5; u++) {
        int id = base + u;
        if (id < N_NODES) { g_off[id] = ex; g_cur[id] = ex; }
        ex += c[u];
    }
    if (t == 0) g_off[N_NODES] = N_EDGES;
}

__global__ void k_scatter(const int* __restrict__ ei) {
    int e = blockIdx.x * blockDim.x + threadIdx.x;
    if (e < N_EDGES) {
        int pos = atomicAdd(&g_cur[ei[e]], 1);
        g_perm[pos] = e;
    }
}

// ---------------- hid = relu(edge_attr @ W1 + b1) ----------------
#define HID_EB 8
__global__ void k_hid(const float* __restrict__ ea,
                      const float* __restrict__ W1,
                      const float* __restrict__ b1) {
    __shared__ float eaS[HID_EB][ED];
    int e0 = blockIdx.x * HID_EB;
    int tid = threadIdx.x;
    if (tid < HID_EB * ED) {
        int e = tid / ED, t = tid % ED;
        eaS[e][t] = ea[(size_t)(e0 + e) * ED + t];
    }
    __syncthreads();
    for (int k = tid; k < H2; k += 256) {
        float acc[HID_EB];
        float bv = b1[k];
#pragma unroll
        for (int e = 0; e < HID_EB; e++) acc[e] = bv;
#pragma unroll
        for (int t = 0; t < ED; t++) {
            float w = W1[t * H2 + k];
#pragma unroll
            for (int e = 0; e < HID_EB; e++) acc[e] = fmaf(eaS[e][t], w, acc[e]);
        }
#pragma unroll
        for (int e = 0; e < HID_EB; e++)
            g_hid[(size_t)(e0 + e) * H2 + k] = fmaxf(acc[e], 0.0f);
    }
}

// ---------------- GEMM1 (tensor-core 3xtf32) ----------------
// M[n, c] = sum_j h[n,j] * W2flat[c*64 + j],  exactness via split-tf32:
//   x = hi + lo (hi = tf32_rna(x), lo = tf32_rna(x - hi))
//   A*B ~= Ah*Bh + Ah*Bl + Al*Bh      (Al*Bl term ~2^-22, negligible)
//
// Block tile: 64 nodes x 128 cols, K = 64.  mma.m16n8k8 tf32.
// smem holds FRAGMENT-ORDERED tiles: one LDS.128 per lane = full fragment.
//   BF[ntile(16)][kstep(8)][lane(32)] = float4(b0h, b1h, b0l, b1l)   64 KB
//   AH/AL[mtile(4)][kstep(8)][lane(32)] = float4(a0..a3)             16+16 KB
#define G1_TC 128
#define G1_TN 64
#define G1_SMEM ((16 * 8 * 32 * 4 + 2 * 4 * 8 * 32 * 4) * 4)   // 98304 B

__global__ void __launch_bounds__(256, 2) k_gemm1(const float* __restrict__ h,
                                                  const float* __restrict__ W2,
                                                  int n_base) {
    extern __shared__ float sm[];
    float* BF = sm;                    // 16384 floats
    float* AH = sm + 16384;            // 4096 floats
    float* AL = sm + 16384 + 4096;     // 4096 floats

    int tid = threadIdx.x;
    int n0 = n_base + blockIdx.y * G1_TN;
    size_t c0 = (size_t)blockIdx.x * G1_TC;

    // ---- fill B fragments (128 cols x 64 j) ----
    for (int idx = tid; idx < G1_TC * 64; idx += 256) {
        int c = idx >> 6, j = idx & 63;
        float v = W2[(c0 + c) * 64 + j];
        float hi = __uint_as_float(tf32_rna(v));
        float lo = __uint_as_float(tf32_rna(v - hi));
        int nt = c >> 3, gid = c & 7;
        int ks = j >> 3, jj = j & 7;
        int tig = jj & 3, slot = jj >> 2;
        int fi = (((nt << 3) + ks) * 32 + (gid << 2) + tig) << 2;
        BF[fi + slot]     = hi;
        BF[fi + 2 + slot] = lo;
    }
    // ---- fill A fragments (64 nodes x 64 j) ----
    for (int idx = tid; idx < G1_TN * 64; idx += 256) {
        int m = idx >> 6, j = idx & 63;
        int n = n0 + m;
        float v = (n < N_NODES) ? h[(size_t)n * 64 + j] : 0.0f;
        float hi = __uint_as_float(tf32_rna(v));
        float lo = __uint_as_float(tf32_rna(v - hi));
        int mt = m >> 4, mm = m & 15;
        int ks = j >> 3, jj = j & 7;
        int reg = (mm >> 3) | ((jj >> 2) << 1);
        int lane = ((mm & 7) << 2) + (jj & 3);
        int ai = (((mt << 3) + ks) * 32 + lane) << 2 | reg;
        AH[ai] = hi;
        AL[ai] = lo;
    }
    __syncthreads();

    int w = tid >> 5, lane = tid & 31;
    int mt = w >> 1;           // m-tile 0..3 (16 nodes each)
    int nw = w & 1;            // col half (64 cols each)

    float acc[8][4];
#pragma unroll
    for (int nt = 0; nt < 8; nt++)
#pragma unroll
        for (int r = 0; r < 4; r++) acc[nt][r] = 0.0f;

#pragma unroll
    for (int ks = 0; ks < 8; ks++) {
        float4 ah = *(const float4*)&AH[(((mt << 3) + ks) * 32 + lane) << 2];
        float4 al = *(const float4*)&AL[(((mt << 3) + ks) * 32 + lane) << 2];
        uint32_t ah0 = __float_as_uint(ah.x), ah1 = __float_as_uint(ah.y);
        uint32_t ah2 = __float_as_uint(ah.z), ah3 = __float_as_uint(ah.w);
        uint32_t al0 = __float_as_uint(al.x), al1 = __float_as_uint(al.y);
        uint32_t al2 = __float_as_uint(al.z), al3 = __float_as_uint(al.w);
#pragma unroll
        for (int nt = 0; nt < 8; nt++) {
            int ntg = (nw << 3) + nt;
            float4 b = *(const float4*)&BF[((((ntg << 3) + ks) * 32) + lane) << 2];
            uint32_t b0h = __float_as_uint(b.x), b1h = __float_as_uint(b.y);
            uint32_t b0l = __float_as_uint(b.z), b1l = __float_as_uint(b.w);
            mma_tf32(acc[nt], ah0, ah1, ah2, ah3, b0h, b1h);   // Ah*Bh
            mma_tf32(acc[nt], ah0, ah1, ah2, ah3, b0l, b1l);   // Ah*Bl
            mma_tf32(acc[nt], al0, al1, al2, al3, b0h, b1h);   // Al*Bh
        }
    }

    // ---- epilogue: write to g_M ----
    int gid = lane >> 2, tig = lane & 3;
    int row0 = (n0 - n_base) + (mt << 4) + gid;    // local row in pass
#pragma unroll
    for (int nt = 0; nt < 8; nt++) {
        size_t col = c0 + (nw << 6) + (nt << 3) + (tig << 1);
        float* p0 = g_M + (size_t)row0 * NCOLS + col;
        *(float2*)p0 = make_float2(acc[nt][0], acc[nt][1]);
        *(float2*)(p0 + (size_t)8 * NCOLS) = make_float2(acc[nt][2], acc[nt][3]);
    }
}

// ---------------- Stage 2: per-node, m[e,i] = sum_k hid[e,k]*M[n,k*64+i] + cb[i] ----------------
__global__ void __launch_bounds__(256) k_stage2(const float* __restrict__ h,
                                                const float* __restrict__ b2,
                                                float* __restrict__ out,
                                                int n_base) {
    __shared__ __align__(16) float Ms[128 * 64];     // 32 KB M chunk [k][i]
    __shared__ __align__(16) float hidS[24 * 128];   // 12 KB hid chunk [slot][k]
    __shared__ float hS[64];
    __shared__ float cb[64];
    __shared__ int eS[24];

    int n = n_base + blockIdx.x;
    if (n >= N_NODES) return;
    int start = g_off[n], end = g_off[n + 1];
    if (start == end) return;

    int tid = threadIdx.x;
    int s = tid >> 5;
    int il = tid & 31;
    int i2 = il * 2;

    if (tid < 64) hS[tid] = h[(size_t)n * 64 + tid];
    __syncthreads();
    if (s == 0) {
        float c0 = 0.f, c1 = 0.f;
#pragma unroll 8
        for (int j = 0; j < 64; j++) {
            float hv = hS[j];
            c0 = fmaf(b2[i2 * 64 + j], hv, c0);
            c1 = fmaf(b2[(i2 + 1) * 64 + j], hv, c1);
        }
        cb[i2] = c0; cb[i2 + 1] = c1;
    }

    const float* Mrow = g_M + (size_t)(n - n_base) * NCOLS;

    for (int base = start; base < end; base += 24) {
        int cnt = min(24, end - base);
        __syncthreads();
        if (tid < cnt) eS[tid] = g_perm[base + tid];
        __syncthreads();

        float2 a0 = make_float2(cb[i2], cb[i2 + 1]);
        float2 a1 = a0, a2 = a0;
        bool v0 = (s < cnt), v1 = (s + 8 < cnt), v2 = (s + 16 < cnt);

        for (int kc = 0; kc < 32; kc++) {
            __syncthreads();
            const float4* msrc = (const float4*)(Mrow + (size_t)kc * 8192);
            for (int u = tid; u < 2048; u += 256) ((float4*)Ms)[u] = msrc[u];
            for (int u = tid; u < cnt * 32; u += 256) {
                int v = u >> 5, q = u & 31;
                const float4* hsrc =
                    (const float4*)(g_hid + (size_t)eS[v] * H2 + kc * 128);
                ((float4*)(hidS + v * 128))[q] = hsrc[q];
            }
            __syncthreads();
            if (v0) {
#pragma unroll 4
                for (int k = 0; k < 128; k++) {
                    float2 mm = *(const float2*)&Ms[k * 64 + i2];
                    float h0 = hidS[s * 128 + k];
                    a0.x = fmaf(h0, mm.x, a0.x);
                    a0.y = fmaf(h0, mm.y, a0.y);
                    if (v1) {
                        float h1 = hidS[(s + 8) * 128 + k];
                        a1.x = fmaf(h1, mm.x, a1.x);
                        a1.y = fmaf(h1, mm.y, a1.y);
                    }
                    if (v2) {
                        float h2v = hidS[(s + 16) * 128 + k];
                        a2.x = fmaf(h2v, mm.x, a2.x);
                        a2.y = fmaf(h2v, mm.y, a2.y);
                    }
                }
            }
        }
        if (v0) *(float2*)&out[(size_t)eS[s] * 64 + i2] = a0;
        if (v1) *(float2*)&out[(size_t)eS[s + 8] * 64 + i2] = a1;
        if (v2) *(float2*)&out[(size_t)eS[s + 16] * 64 + i2] = a2;
    }
}

// ---------------- dst passthrough (second tuple element, as float) ----------------
__global__ void k_dst(const int* __restrict__ ei, float* __restrict__ out) {
    int e = blockIdx.x * blockDim.x + threadIdx.x;
    if (e < N_EDGES) out[(size_t)N_EDGES * 64 + e] = (float)ei[N_EDGES + e];
}

// ---------------- launch ----------------
extern "C" void kernel_launch(void* const* d_in, const int* in_sizes, int n_in,
                              void* d_out, int out_size) {
    const float* h  = (const float*)d_in[0];
    const int*   ei = (const int*)d_in[1];
    const float* ea = (const float*)d_in[2];
    const float* W1 = (const float*)d_in[3];
    const float* b1 = (const float*)d_in[4];
    const float* W2 = (const float*)d_in[5];
    const float* b2 = (const float*)d_in[6];
    float* out = (float*)d_out;

    // CSR by src
    k_zero_cnt<<<(N_NODES + 255) / 256, 256>>>();
    k_hist<<<(N_EDGES + 255) / 256, 256>>>(ei);
    k_scan<<<1, 1024>>>();
    k_scatter<<<(N_EDGES + 255) / 256, 256>>>(ei);

    // hid
    k_hid<<<N_EDGES / HID_EB, 256>>>(ea, W1, b1);

    cudaFuncSetAttribute(k_gemm1, cudaFuncAttributeMaxDynamicSharedMemorySize,
                         G1_SMEM);

    // node passes through the reusable M scratch
    for (int p = 0; p < N_PASSES; p++) {
        int n_base = p * PASS_NODES;
        dim3 g1(NCOLS / G1_TC, PASS_NODES / G1_TN);
        k_gemm1<<<g1, 256, G1_SMEM>>>(h, W2, n_base);
        k_stage2<<<PASS_NODES, 256>>>(h, b2, out, n_base);
    }

    if (out_size > N_EDGES * 64)
        k_dst<<<(N_EDGES + 255) / 256, 256>>>(ei, out);
}